// round 1
// baseline (speedup 1.0000x reference)
#include <cuda_runtime.h>
#include <math.h>

#define NN    50000      // nodes
#define NE    800000     // edges
#define NG    512        // graphs
#define HID   128
#define RBF   32
#define NL    6
#define TBL   5120       // LUT grid points per layer
#define DMAX  5.0f       // beyond this, rbf == 0 to fp32 precision

// ---------------- device scratch (static allocations only) ----------------
__device__ float g_h    [NN * HID];        // node features
__device__ float g_aggr [NN * HID];        // aggregated messages / e2 reuse
__device__ float g_table[NL * TBL * HID];  // W_l(d) lookup table
__device__ int   g_deg  [NN];
__device__ float g_invd [NN];
__device__ int   g_off  [NN + 1];
__device__ int   g_cur  [NN];
__device__ int   g_sj   [NE];              // CSR: neighbor j
__device__ float g_st   [NE];              // CSR: d scaled to table coords
__device__ int   g_se   [NE];              // CSR: original edge id (sort key)

__device__ __forceinline__ float sspf(float x) {
    // softplus(x) - 0.5, numerically stable (matches jax.nn.softplus in fp32)
    return fmaxf(x, 0.0f) + log1pf(expf(-fabsf(x))) - 0.5f;
}

// ---------------- init: h = embed[z], zero deg ----------------
__global__ void k_init(const int* __restrict__ z, const float* __restrict__ embed) {
    int tid  = blockIdx.x * blockDim.x + threadIdx.x;   // NN*32 threads exactly
    int n    = tid >> 5;
    int lane = tid & 31;
    if (lane == 0) g_deg[n] = 0;
    int zz = z[n];
    float4 v = *(const float4*)(embed + (size_t)zz * HID + lane * 4);
    *(float4*)(g_h + (size_t)n * HID + lane * 4) = v;
}

// ---------------- degree count ----------------
__global__ void k_deg(const int* __restrict__ ei) {
    int e = blockIdx.x * blockDim.x + threadIdx.x;      // NE threads exactly
    atomicAdd(&g_deg[ei[e]], 1);
}

// ---------------- single-block exclusive scan over degrees ----------------
__global__ void k_scan() {
    __shared__ int sums[1024];
    const int t = threadIdx.x;
    const int CH = 49;                                  // 1024*49 >= NN
    int base = t * CH;
    int s = 0;
    for (int u = 0; u < CH; u++) {
        int idx = base + u;
        if (idx < NN) s += g_deg[idx];
    }
    sums[t] = s;
    __syncthreads();
    for (int o = 1; o < 1024; o <<= 1) {
        int v = (t >= o) ? sums[t - o] : 0;
        __syncthreads();
        sums[t] += v;
        __syncthreads();
    }
    int run = (t == 0) ? 0 : sums[t - 1];
    for (int u = 0; u < CH; u++) {
        int idx = base + u;
        if (idx < NN) {
            int d = g_deg[idx];
            g_off[idx] = run;
            g_cur[idx] = run;
            g_invd[idx] = 1.0f / (float)max(d, 1);
            run += d;
        }
    }
    if (t == 1023) g_off[NN] = sums[1023];
}

// ---------------- compute d, scatter edges into CSR buckets ----------------
__global__ void k_scatter(const int* __restrict__ ei, const float* __restrict__ pos) {
    int e = blockIdx.x * blockDim.x + threadIdx.x;      // NE threads exactly
    int i = ei[e];
    int j = ei[NE + e];
    float dx = pos[3 * i + 0] - pos[3 * j + 0];
    float dy = pos[3 * i + 1] - pos[3 * j + 1];
    float dz = pos[3 * i + 2] - pos[3 * j + 2];
    float d  = sqrtf(dx * dx + dy * dy + dz * dz);
    const float inv_step = (float)(TBL - 1) / DMAX;
    float tt = fminf(d * inv_step, (float)(TBL - 1));
    int p = atomicAdd(&g_cur[i], 1);
    g_sj[p] = j;
    g_st[p] = tt;
    g_se[p] = e;
}

// ---------------- deterministic order: insertion sort each bucket by edge id ----
__global__ void k_sort() {
    int n = blockIdx.x * blockDim.x + threadIdx.x;
    if (n >= NN) return;
    int lo = g_off[n], hi = g_off[n + 1];
    for (int a = lo + 1; a < hi; a++) {
        int   ke = g_se[a];
        int   kj = g_sj[a];
        float kt = g_st[a];
        int b = a - 1;
        while (b >= lo && g_se[b] > ke) {
            g_se[b + 1] = g_se[b];
            g_sj[b + 1] = g_sj[b];
            g_st[b + 1] = g_st[b];
            b--;
        }
        g_se[b + 1] = ke;
        g_sj[b + 1] = kj;
        g_st[b + 1] = kt;
    }
}

// ---------------- build W_l(d) table: 8 grid points per block ----------------
__global__ void k_table(const float* __restrict__ fw1, const float* __restrict__ fb1,
                        const float* __restrict__ fw2, const float* __restrict__ fb2) {
    const int PG = 8;
    int gid = blockIdx.x * PG;          // over NL*TBL
    int l   = gid / TBL;
    int g0  = gid - l * TBL;
    int c   = threadIdx.x;              // 128 threads
    __shared__ float rbf [PG][RBF];
    __shared__ float sspt[PG][HID];
    const float step   = DMAX / (float)(TBL - 1);
    const float cspace = 4.0f / 31.0f;

    for (int u = c; u < PG * RBF; u += HID) {
        int p = u >> 5, k = u & 31;
        float d = (float)(g0 + p) * step;
        float x = d - (float)k * cspace;
        rbf[p][k] = expf(-32.0f * x * x);
    }
    __syncthreads();

    float acc[PG];
    float b1 = fb1[l * HID + c];
    #pragma unroll
    for (int p = 0; p < PG; p++) acc[p] = b1;
    for (int k = 0; k < RBF; k++) {
        float f = fw1[(size_t)(l * RBF + k) * HID + c];
        #pragma unroll
        for (int p = 0; p < PG; p++) acc[p] = fmaf(rbf[p][k], f, acc[p]);
    }
    #pragma unroll
    for (int p = 0; p < PG; p++) sspt[p][c] = sspf(acc[p]);
    __syncthreads();

    float b2 = fb2[l * HID + c];
    #pragma unroll
    for (int p = 0; p < PG; p++) acc[p] = b2;
    for (int m = 0; m < HID; m++) {
        float f = fw2[(size_t)(l * HID + m) * HID + c];
        #pragma unroll
        for (int p = 0; p < PG; p++) acc[p] = fmaf(sspt[p][m], f, acc[p]);
    }
    #pragma unroll
    for (int p = 0; p < PG; p++)
        g_table[((size_t)l * TBL + g0 + p) * HID + c] = acc[p];
}

// ---------------- per-layer edge aggregation: one warp per node -------------
__global__ void k_edge(int l) {
    int w    = (blockIdx.x * blockDim.x + threadIdx.x) >> 5;  // == node, exact
    int lane = threadIdx.x & 31;
    int lo = g_off[w], hi = g_off[w + 1];
    const float* tab = g_table + (size_t)l * TBL * HID;
    float ax = 0.f, ay = 0.f, az = 0.f, aw = 0.f;
    for (int e = lo; e < hi; e++) {
        int   j  = __ldg(&g_sj[e]);
        float tt = __ldg(&g_st[e]);
        int   idx = min((int)tt, TBL - 2);
        float fr  = tt - (float)idx;
        float4 wl = *(const float4*)(tab + (size_t)idx * HID + lane * 4);
        float4 wh = *(const float4*)(tab + (size_t)idx * HID + HID + lane * 4);
        float4 hj = *(const float4*)(g_h + (size_t)j * HID + lane * 4);
        ax = fmaf(hj.x, fmaf(fr, wh.x - wl.x, wl.x), ax);
        ay = fmaf(hj.y, fmaf(fr, wh.y - wl.y, wl.y), ay);
        az = fmaf(hj.z, fmaf(fr, wh.z - wl.z, wl.z), az);
        aw = fmaf(hj.w, fmaf(fr, wh.w - wl.w, wl.w), aw);
    }
    float s = g_invd[w];
    float4 o = make_float4(ax * s, ay * s, az * s, aw * s);
    *(float4*)(g_aggr + (size_t)w * HID + lane * 4) = o;
}

// ------------- fused 2-layer MLP: Y = act2( ssp(X@W1+b1) @ W2 + b2 ) --------
template <int ACT2>
__global__ void k_mlp(const float* __restrict__ X,
                      const float* __restrict__ W1, const float* __restrict__ B1,
                      const float* __restrict__ W2, const float* __restrict__ B2,
                      float* __restrict__ Y, int nrows) {
    __shared__ float As[64 * HID];
    const int tid = threadIdx.x;
    const int tr = tid >> 4;            // 0..15 -> 4 rows each
    const int tc = tid & 15;            // 0..15 -> 8 cols each
    const int row0 = blockIdx.x * 64;

    for (int u = tid; u < 64 * (HID / 4); u += 256) {
        int r = u >> 5, q = u & 31;
        int gr = row0 + r;
        float4 v = make_float4(0.f, 0.f, 0.f, 0.f);
        if (gr < nrows) v = *(const float4*)(X + (size_t)gr * HID + q * 4);
        *(float4*)(As + r * HID + q * 4) = v;
    }
    __syncthreads();

    float acc[4][8];
    #pragma unroll
    for (int a = 0; a < 4; a++)
        #pragma unroll
        for (int b = 0; b < 8; b++) acc[a][b] = 0.f;

    #pragma unroll 4
    for (int k = 0; k < HID; k++) {
        float a0 = As[(tr * 4 + 0) * HID + k];
        float a1 = As[(tr * 4 + 1) * HID + k];
        float a2 = As[(tr * 4 + 2) * HID + k];
        float a3 = As[(tr * 4 + 3) * HID + k];
        float4 b0 = __ldg((const float4*)(W1 + (size_t)k * HID + tc * 8));
        float4 b1 = __ldg((const float4*)(W1 + (size_t)k * HID + tc * 8 + 4));
        float bb[8] = {b0.x, b0.y, b0.z, b0.w, b1.x, b1.y, b1.z, b1.w};
        #pragma unroll
        for (int c = 0; c < 8; c++) {
            acc[0][c] = fmaf(a0, bb[c], acc[0][c]);
            acc[1][c] = fmaf(a1, bb[c], acc[1][c]);
            acc[2][c] = fmaf(a2, bb[c], acc[2][c]);
            acc[3][c] = fmaf(a3, bb[c], acc[3][c]);
        }
    }
    float4 c0 = __ldg((const float4*)(B1 + tc * 8));
    float4 c1 = __ldg((const float4*)(B1 + tc * 8 + 4));
    float bias1[8] = {c0.x, c0.y, c0.z, c0.w, c1.x, c1.y, c1.z, c1.w};
    __syncthreads();   // all stage-1 reads of As done
    #pragma unroll
    for (int rr = 0; rr < 4; rr++) {
        float4 s0, s1;
        s0.x = sspf(acc[rr][0] + bias1[0]);
        s0.y = sspf(acc[rr][1] + bias1[1]);
        s0.z = sspf(acc[rr][2] + bias1[2]);
        s0.w = sspf(acc[rr][3] + bias1[3]);
        s1.x = sspf(acc[rr][4] + bias1[4]);
        s1.y = sspf(acc[rr][5] + bias1[5]);
        s1.z = sspf(acc[rr][6] + bias1[6]);
        s1.w = sspf(acc[rr][7] + bias1[7]);
        *(float4*)(As + (tr * 4 + rr) * HID + tc * 8)     = s0;
        *(float4*)(As + (tr * 4 + rr) * HID + tc * 8 + 4) = s1;
    }
    __syncthreads();

    #pragma unroll
    for (int a = 0; a < 4; a++)
        #pragma unroll
        for (int b = 0; b < 8; b++) acc[a][b] = 0.f;

    #pragma unroll 4
    for (int k = 0; k < HID; k++) {
        float a0 = As[(tr * 4 + 0) * HID + k];
        float a1 = As[(tr * 4 + 1) * HID + k];
        float a2 = As[(tr * 4 + 2) * HID + k];
        float a3 = As[(tr * 4 + 3) * HID + k];
        float4 b0 = __ldg((const float4*)(W2 + (size_t)k * HID + tc * 8));
        float4 b1 = __ldg((const float4*)(W2 + (size_t)k * HID + tc * 8 + 4));
        float bb[8] = {b0.x, b0.y, b0.z, b0.w, b1.x, b1.y, b1.z, b1.w};
        #pragma unroll
        for (int c = 0; c < 8; c++) {
            acc[0][c] = fmaf(a0, bb[c], acc[0][c]);
            acc[1][c] = fmaf(a1, bb[c], acc[1][c]);
            acc[2][c] = fmaf(a2, bb[c], acc[2][c]);
            acc[3][c] = fmaf(a3, bb[c], acc[3][c]);
        }
    }
    float4 d0 = __ldg((const float4*)(B2 + tc * 8));
    float4 d1 = __ldg((const float4*)(B2 + tc * 8 + 4));
    float bias2[8] = {d0.x, d0.y, d0.z, d0.w, d1.x, d1.y, d1.z, d1.w};

    #pragma unroll
    for (int rr = 0; rr < 4; rr++) {
        int gr = row0 + tr * 4 + rr;
        if (gr >= nrows) continue;
        float v[8];
        #pragma unroll
        for (int c = 0; c < 8; c++) {
            float t = acc[rr][c] + bias2[c];
            v[c] = (ACT2 ? sspf(t) : t);
        }
        float4 o0 = make_float4(v[0], v[1], v[2], v[3]);
        float4 o1 = make_float4(v[4], v[5], v[6], v[7]);
        *(float4*)(Y + (size_t)gr * HID + tc * 8)     = o0;
        *(float4*)(Y + (size_t)gr * HID + tc * 8 + 4) = o1;
    }
}

// ---------------- output reduction ----------------
__global__ void k_zero_out(float* out) {
    int g = blockIdx.x * blockDim.x + threadIdx.x;
    if (g < NG) out[g] = 0.0f;
}

__global__ void k_energy(const int* __restrict__ batch,
                         const float* __restrict__ ow3, const float* __restrict__ ob3,
                         float* __restrict__ out) {
    int w    = (blockIdx.x * blockDim.x + threadIdx.x) >> 5;   // node
    int lane = threadIdx.x & 31;
    float4 e  = *(const float4*)(g_aggr + (size_t)w * HID + lane * 4);
    float4 ww = *(const float4*)(ow3 + lane * 4);
    float v = e.x * ww.x + e.y * ww.y + e.z * ww.z + e.w * ww.w;
    #pragma unroll
    for (int o = 16; o > 0; o >>= 1) v += __shfl_down_sync(0xffffffffu, v, o);
    if (lane == 0) atomicAdd(&out[batch[w]], v + ob3[0]);
}

// ---------------- launch ----------------
extern "C" void kernel_launch(void* const* d_in, const int* in_sizes, int n_in,
                              void* d_out, int out_size) {
    const int*   z     = (const int*)  d_in[0];
    const float* pos   = (const float*)d_in[1];
    const int*   ei    = (const int*)  d_in[2];
    const int*   batch = (const int*)  d_in[3];
    const float* embed = (const float*)d_in[4];
    const float* fw1   = (const float*)d_in[5];
    const float* fb1   = (const float*)d_in[6];
    const float* fw2   = (const float*)d_in[7];
    const float* fb2   = (const float*)d_in[8];
    const float* uw1   = (const float*)d_in[9];
    const float* ub1   = (const float*)d_in[10];
    const float* uw2   = (const float*)d_in[11];
    const float* ub2   = (const float*)d_in[12];
    const float* ow1   = (const float*)d_in[13];
    const float* ob1   = (const float*)d_in[14];
    const float* ow2   = (const float*)d_in[15];
    const float* ob2   = (const float*)d_in[16];
    const float* ow3   = (const float*)d_in[17];
    const float* ob3   = (const float*)d_in[18];
    float* out = (float*)d_out;

    float *p_h = nullptr, *p_aggr = nullptr;
    cudaGetSymbolAddress((void**)&p_h,    g_h);
    cudaGetSymbolAddress((void**)&p_aggr, g_aggr);

    // preprocessing (once per launch, amortized over 6 layers)
    k_init   <<<(NN * 32) / 256, 256>>>(z, embed);
    k_deg    <<<NE / 256, 256>>>(ei);
    k_scan   <<<1, 1024>>>();
    k_scatter<<<NE / 256, 256>>>(ei, pos);
    k_sort   <<<(NN + 255) / 256, 256>>>();
    k_table  <<<(NL * TBL) / 8, 128>>>(fw1, fb1, fw2, fb2);

    const int mlp_blocks  = (NN + 63) / 64;
    const int warp_blocks = (NN * 32) / 256;

    for (int l = 0; l < NL; l++) {
        k_edge<<<warp_blocks, 256>>>(l);
        k_mlp<0><<<mlp_blocks, 256>>>(p_aggr,
                                      uw1 + (size_t)l * HID * HID, ub1 + (size_t)l * HID,
                                      uw2 + (size_t)l * HID * HID, ub2 + (size_t)l * HID,
                                      p_h, NN);
    }
    // output block: e2 = ssp(ssp(h@ow1+b1)@ow2+b2) stored into g_aggr
    k_mlp<1><<<mlp_blocks, 256>>>(p_h, ow1, ob1, ow2, ob2, p_aggr, NN);
    k_zero_out<<<2, 256>>>(out);
    k_energy<<<warp_blocks, 256>>>(batch, ow3, ob3, out);
}

// round 2
// speedup vs baseline: 1.1470x; 1.1470x over previous
#include <cuda_runtime.h>
#include <math.h>

#define NN    50000      // nodes
#define NE    800000     // edges
#define NG    512        // graphs
#define HID   128
#define RBF   32
#define NL    6
#define TBL   5120       // LUT grid points per layer
#define DMAX  5.0f       // beyond this, rbf == 0 to fp32 precision

typedef unsigned long long u64;

// ---------------- device scratch (static allocations only) ----------------
__device__ float g_h    [NN * HID];        // node features
__device__ float g_aggr [NN * HID];        // aggregated messages / e2 reuse
__device__ float g_table[NL * TBL * HID];  // W_l(d) lookup table
__device__ int   g_deg  [NN];
__device__ float g_invd [NN];
__device__ int   g_off  [NN + 1];
__device__ int   g_cur  [NN];
__device__ int2  g_jt   [NE];              // CSR: {neighbor j, tt bits}
__device__ int   g_se   [NE];              // CSR: original edge id (sort key)

__device__ __forceinline__ float sspf(float x) {
    return fmaxf(x, 0.0f) + log1pf(expf(-fabsf(x))) - 0.5f;
}

__device__ __forceinline__ u64 pack2(float lo, float hi) {
    u64 r;
    asm("mov.b64 %0, {%1, %2};" : "=l"(r) : "f"(lo), "f"(hi));
    return r;
}
__device__ __forceinline__ void unpack2(u64 v, float& lo, float& hi) {
    asm("mov.b64 {%0, %1}, %2;" : "=f"(lo), "=f"(hi) : "l"(v));
}
__device__ __forceinline__ void ffma2(u64& d, u64 a, u64 b) {
    asm("fma.rn.f32x2 %0, %1, %2, %0;" : "+l"(d) : "l"(a), "l"(b));
}

// ---------------- init: h = embed[z], zero deg ----------------
__global__ void k_init(const int* __restrict__ z, const float* __restrict__ embed) {
    int tid  = blockIdx.x * blockDim.x + threadIdx.x;   // NN*32 threads exactly
    int n    = tid >> 5;
    int lane = tid & 31;
    if (lane == 0) g_deg[n] = 0;
    int zz = z[n];
    float4 v = *(const float4*)(embed + (size_t)zz * HID + lane * 4);
    *(float4*)(g_h + (size_t)n * HID + lane * 4) = v;
}

// ---------------- degree count ----------------
__global__ void k_deg(const int* __restrict__ ei) {
    int e = blockIdx.x * blockDim.x + threadIdx.x;      // NE threads exactly
    atomicAdd(&g_deg[ei[e]], 1);
}

// ---------------- single-block exclusive scan over degrees ----------------
__global__ void k_scan() {
    __shared__ int sums[1024];
    const int t = threadIdx.x;
    const int CH = 49;                                  // 1024*49 >= NN
    int base = t * CH;
    int s = 0;
    for (int u = 0; u < CH; u++) {
        int idx = base + u;
        if (idx < NN) s += g_deg[idx];
    }
    sums[t] = s;
    __syncthreads();
    for (int o = 1; o < 1024; o <<= 1) {
        int v = (t >= o) ? sums[t - o] : 0;
        __syncthreads();
        sums[t] += v;
        __syncthreads();
    }
    int run = (t == 0) ? 0 : sums[t - 1];
    for (int u = 0; u < CH; u++) {
        int idx = base + u;
        if (idx < NN) {
            int d = g_deg[idx];
            g_off[idx] = run;
            g_cur[idx] = run;
            g_invd[idx] = 1.0f / (float)max(d, 1);
            run += d;
        }
    }
    if (t == 1023) g_off[NN] = sums[1023];
}

// ---------------- compute d, scatter edges into CSR buckets ----------------
__global__ void k_scatter(const int* __restrict__ ei, const float* __restrict__ pos) {
    int e = blockIdx.x * blockDim.x + threadIdx.x;      // NE threads exactly
    int i = ei[e];
    int j = ei[NE + e];
    float dx = pos[3 * i + 0] - pos[3 * j + 0];
    float dy = pos[3 * i + 1] - pos[3 * j + 1];
    float dz = pos[3 * i + 2] - pos[3 * j + 2];
    float d  = sqrtf(dx * dx + dy * dy + dz * dz);
    const float inv_step = (float)(TBL - 1) / DMAX;
    float tt = fminf(d * inv_step, (float)(TBL - 1));
    int p = atomicAdd(&g_cur[i], 1);
    g_jt[p] = make_int2(j, __float_as_int(tt));
    g_se[p] = e;
}

// --------- deterministic order: insertion sort each bucket by edge id ------
__global__ void k_sort() {
    int n = blockIdx.x * blockDim.x + threadIdx.x;
    if (n >= NN) return;
    int lo = g_off[n], hi = g_off[n + 1];
    for (int a = lo + 1; a < hi; a++) {
        int  ke = g_se[a];
        int2 kv = g_jt[a];
        int b = a - 1;
        while (b >= lo && g_se[b] > ke) {
            g_se[b + 1] = g_se[b];
            g_jt[b + 1] = g_jt[b];
            b--;
        }
        g_se[b + 1] = ke;
        g_jt[b + 1] = kv;
    }
}

// ---------------- build W_l(d) table: 8 grid points per block --------------
__global__ void k_table(const float* __restrict__ fw1, const float* __restrict__ fb1,
                        const float* __restrict__ fw2, const float* __restrict__ fb2) {
    const int PG = 8;
    int gid = blockIdx.x * PG;          // over NL*TBL
    int l   = gid / TBL;
    int g0  = gid - l * TBL;
    int c   = threadIdx.x;              // 128 threads
    __shared__ float rbf [PG][RBF];
    __shared__ float sspt[PG][HID];
    const float step   = DMAX / (float)(TBL - 1);
    const float cspace = 4.0f / 31.0f;

    for (int u = c; u < PG * RBF; u += HID) {
        int p = u >> 5, k = u & 31;
        float d = (float)(g0 + p) * step;
        float x = d - (float)k * cspace;
        rbf[p][k] = expf(-32.0f * x * x);
    }
    __syncthreads();

    float acc[PG];
    float b1 = fb1[l * HID + c];
    #pragma unroll
    for (int p = 0; p < PG; p++) acc[p] = b1;
    for (int k = 0; k < RBF; k++) {
        float f = fw1[(size_t)(l * RBF + k) * HID + c];
        #pragma unroll
        for (int p = 0; p < PG; p++) acc[p] = fmaf(rbf[p][k], f, acc[p]);
    }
    #pragma unroll
    for (int p = 0; p < PG; p++) sspt[p][c] = sspf(acc[p]);
    __syncthreads();

    float b2 = fb2[l * HID + c];
    #pragma unroll
    for (int p = 0; p < PG; p++) acc[p] = b2;
    for (int m = 0; m < HID; m++) {
        float f = fw2[(size_t)(l * HID + m) * HID + c];
        #pragma unroll
        for (int p = 0; p < PG; p++) acc[p] = fmaf(sspt[p][m], f, acc[p]);
    }
    #pragma unroll
    for (int p = 0; p < PG; p++)
        g_table[((size_t)l * TBL + g0 + p) * HID + c] = acc[p];
}

// --------- per-layer edge aggregation: one warp per node, far fast path ----
__global__ void k_edge(int l) {
    int w    = (blockIdx.x * blockDim.x + threadIdx.x) >> 5;  // == node, exact
    int lane = threadIdx.x & 31;
    int lo = g_off[w], hi = g_off[w + 1];
    const float* tab = g_table + (size_t)l * TBL * HID;
    // far edges (d >= DMAX) all hit the constant last table row
    const float4 wlast = *(const float4*)(tab + (size_t)(TBL - 1) * HID + lane * 4);
    const float TTMAX = (float)(TBL - 1);
    float nx = 0.f, ny = 0.f, nz = 0.f, nw = 0.f;   // near accum (lerped)
    float fx = 0.f, fy = 0.f, fz = 0.f, fw = 0.f;   // far accum (h sum)
    for (int e = lo; e < hi; e++) {
        int2  jt = __ldg(&g_jt[e]);
        int   j  = jt.x;
        float tt = __int_as_float(jt.y);
        float4 hj = *(const float4*)(g_h + (size_t)j * HID + lane * 4);
        if (tt >= TTMAX) {                           // lane-uniform branch
            fx += hj.x; fy += hj.y; fz += hj.z; fw += hj.w;
        } else {
            int   idx = (int)tt;
            float fr  = tt - (float)idx;
            float4 wl = *(const float4*)(tab + (size_t)idx * HID + lane * 4);
            float4 wh = *(const float4*)(tab + (size_t)idx * HID + HID + lane * 4);
            nx = fmaf(hj.x, fmaf(fr, wh.x - wl.x, wl.x), nx);
            ny = fmaf(hj.y, fmaf(fr, wh.y - wl.y, wl.y), ny);
            nz = fmaf(hj.z, fmaf(fr, wh.z - wl.z, wl.z), nz);
            nw = fmaf(hj.w, fmaf(fr, wh.w - wl.w, wl.w), nw);
        }
    }
    float s = g_invd[w];
    float4 o;
    o.x = fmaf(fx, wlast.x, nx) * s;
    o.y = fmaf(fy, wlast.y, ny) * s;
    o.z = fmaf(fz, wlast.z, nz) * s;
    o.w = fmaf(fw, wlast.w, nw) * s;
    *(float4*)(g_aggr + (size_t)w * HID + lane * 4) = o;
}

// ------ fused 2-layer MLP with packed f32x2 FMAs:
// ------ Y = act2( ssp(X@W1+b1) @ W2 + b2 )
template <int ACT2>
__global__ void k_mlp(const float* __restrict__ X,
                      const float* __restrict__ W1, const float* __restrict__ B1,
                      const float* __restrict__ W2, const float* __restrict__ B2,
                      float* __restrict__ Y, int nrows) {
    __shared__ float As[64 * HID];
    const int tid = threadIdx.x;
    const int tr = tid >> 4;            // 0..15 -> 4 rows each
    const int tc = tid & 15;            // 0..15 -> 8 cols each
    const int row0 = blockIdx.x * 64;

    for (int u = tid; u < 64 * (HID / 4); u += 256) {
        int r = u >> 5, q = u & 31;
        int gr = row0 + r;
        float4 v = make_float4(0.f, 0.f, 0.f, 0.f);
        if (gr < nrows) v = *(const float4*)(X + (size_t)gr * HID + q * 4);
        *(float4*)(As + r * HID + q * 4) = v;
    }
    __syncthreads();

    u64 acc[4][4];                       // [row][col-pair], each holds 2 fp32

    // ---------------- stage 1 ----------------
    #pragma unroll
    for (int a = 0; a < 4; a++)
        #pragma unroll
        for (int b = 0; b < 4; b++) acc[a][b] = 0ull;

    for (int k = 0; k < HID; k += 4) {
        float av[4][4];
        #pragma unroll
        for (int r = 0; r < 4; r++) {
            float4 t = *(const float4*)(As + (tr * 4 + r) * HID + k);
            av[r][0] = t.x; av[r][1] = t.y; av[r][2] = t.z; av[r][3] = t.w;
        }
        #pragma unroll
        for (int kk = 0; kk < 4; kk++) {
            const ulonglong2* wp =
                (const ulonglong2*)(W1 + (size_t)(k + kk) * HID + tc * 8);
            ulonglong2 w0 = __ldg(wp);
            ulonglong2 w1 = __ldg(wp + 1);
            u64 bp0 = w0.x, bp1 = w0.y, bp2 = w1.x, bp3 = w1.y;
            #pragma unroll
            for (int r = 0; r < 4; r++) {
                u64 ap = pack2(av[r][kk], av[r][kk]);
                ffma2(acc[r][0], ap, bp0);
                ffma2(acc[r][1], ap, bp1);
                ffma2(acc[r][2], ap, bp2);
                ffma2(acc[r][3], ap, bp3);
            }
        }
    }
    float4 c0 = __ldg((const float4*)(B1 + tc * 8));
    float4 c1 = __ldg((const float4*)(B1 + tc * 8 + 4));
    float bias1[8] = {c0.x, c0.y, c0.z, c0.w, c1.x, c1.y, c1.z, c1.w};
    __syncthreads();   // all stage-1 reads of As done
    #pragma unroll
    for (int rr = 0; rr < 4; rr++) {
        float v[8];
        #pragma unroll
        for (int p = 0; p < 4; p++) unpack2(acc[rr][p], v[2 * p], v[2 * p + 1]);
        float4 s0, s1;
        s0.x = sspf(v[0] + bias1[0]);
        s0.y = sspf(v[1] + bias1[1]);
        s0.z = sspf(v[2] + bias1[2]);
        s0.w = sspf(v[3] + bias1[3]);
        s1.x = sspf(v[4] + bias1[4]);
        s1.y = sspf(v[5] + bias1[5]);
        s1.z = sspf(v[6] + bias1[6]);
        s1.w = sspf(v[7] + bias1[7]);
        *(float4*)(As + (tr * 4 + rr) * HID + tc * 8)     = s0;
        *(float4*)(As + (tr * 4 + rr) * HID + tc * 8 + 4) = s1;
    }
    __syncthreads();

    // ---------------- stage 2 ----------------
    #pragma unroll
    for (int a = 0; a < 4; a++)
        #pragma unroll
        for (int b = 0; b < 4; b++) acc[a][b] = 0ull;

    for (int k = 0; k < HID; k += 4) {
        float av[4][4];
        #pragma unroll
        for (int r = 0; r < 4; r++) {
            float4 t = *(const float4*)(As + (tr * 4 + r) * HID + k);
            av[r][0] = t.x; av[r][1] = t.y; av[r][2] = t.z; av[r][3] = t.w;
        }
        #pragma unroll
        for (int kk = 0; kk < 4; kk++) {
            const ulonglong2* wp =
                (const ulonglong2*)(W2 + (size_t)(k + kk) * HID + tc * 8);
            ulonglong2 w0 = __ldg(wp);
            ulonglong2 w1 = __ldg(wp + 1);
            u64 bp0 = w0.x, bp1 = w0.y, bp2 = w1.x, bp3 = w1.y;
            #pragma unroll
            for (int r = 0; r < 4; r++) {
                u64 ap = pack2(av[r][kk], av[r][kk]);
                ffma2(acc[r][0], ap, bp0);
                ffma2(acc[r][1], ap, bp1);
                ffma2(acc[r][2], ap, bp2);
                ffma2(acc[r][3], ap, bp3);
            }
        }
    }
    float4 d0 = __ldg((const float4*)(B2 + tc * 8));
    float4 d1 = __ldg((const float4*)(B2 + tc * 8 + 4));
    float bias2[8] = {d0.x, d0.y, d0.z, d0.w, d1.x, d1.y, d1.z, d1.w};

    #pragma unroll
    for (int rr = 0; rr < 4; rr++) {
        int gr = row0 + tr * 4 + rr;
        if (gr >= nrows) continue;
        float v[8];
        #pragma unroll
        for (int p = 0; p < 4; p++) unpack2(acc[rr][p], v[2 * p], v[2 * p + 1]);
        #pragma unroll
        for (int c = 0; c < 8; c++) {
            float t = v[c] + bias2[c];
            v[c] = (ACT2 ? sspf(t) : t);
        }
        float4 o0 = make_float4(v[0], v[1], v[2], v[3]);
        float4 o1 = make_float4(v[4], v[5], v[6], v[7]);
        *(float4*)(Y + (size_t)gr * HID + tc * 8)     = o0;
        *(float4*)(Y + (size_t)gr * HID + tc * 8 + 4) = o1;
    }
}

// ---------------- output reduction ----------------
__global__ void k_zero_out(float* out) {
    int g = blockIdx.x * blockDim.x + threadIdx.x;
    if (g < NG) out[g] = 0.0f;
}

__global__ void k_energy(const int* __restrict__ batch,
                         const float* __restrict__ ow3, const float* __restrict__ ob3,
                         float* __restrict__ out) {
    int w    = (blockIdx.x * blockDim.x + threadIdx.x) >> 5;   // node
    int lane = threadIdx.x & 31;
    float4 e  = *(const float4*)(g_aggr + (size_t)w * HID + lane * 4);
    float4 ww = *(const float4*)(ow3 + lane * 4);
    float v = e.x * ww.x + e.y * ww.y + e.z * ww.z + e.w * ww.w;
    #pragma unroll
    for (int o = 16; o > 0; o >>= 1) v += __shfl_down_sync(0xffffffffu, v, o);
    if (lane == 0) atomicAdd(&out[batch[w]], v + ob3[0]);
}

// ---------------- launch ----------------
extern "C" void kernel_launch(void* const* d_in, const int* in_sizes, int n_in,
                              void* d_out, int out_size) {
    const int*   z     = (const int*)  d_in[0];
    const float* pos   = (const float*)d_in[1];
    const int*   ei    = (const int*)  d_in[2];
    const int*   batch = (const int*)  d_in[3];
    const float* embed = (const float*)d_in[4];
    const float* fw1   = (const float*)d_in[5];
    const float* fb1   = (const float*)d_in[6];
    const float* fw2   = (const float*)d_in[7];
    const float* fb2   = (const float*)d_in[8];
    const float* uw1   = (const float*)d_in[9];
    const float* ub1   = (const float*)d_in[10];
    const float* uw2   = (const float*)d_in[11];
    const float* ub2   = (const float*)d_in[12];
    const float* ow1   = (const float*)d_in[13];
    const float* ob1   = (const float*)d_in[14];
    const float* ow2   = (const float*)d_in[15];
    const float* ob2   = (const float*)d_in[16];
    const float* ow3   = (const float*)d_in[17];
    const float* ob3   = (const float*)d_in[18];
    float* out = (float*)d_out;

    float *p_h = nullptr, *p_aggr = nullptr;
    cudaGetSymbolAddress((void**)&p_h,    g_h);
    cudaGetSymbolAddress((void**)&p_aggr, g_aggr);

    // preprocessing (once per launch, amortized over 6 layers)
    k_init   <<<(NN * 32) / 256, 256>>>(z, embed);
    k_deg    <<<NE / 256, 256>>>(ei);
    k_scan   <<<1, 1024>>>();
    k_scatter<<<NE / 256, 256>>>(ei, pos);
    k_sort   <<<(NN + 255) / 256, 256>>>();
    k_table  <<<(NL * TBL) / 8, 128>>>(fw1, fb1, fw2, fb2);

    const int mlp_blocks  = (NN + 63) / 64;
    const int warp_blocks = (NN * 32) / 256;

    for (int l = 0; l < NL; l++) {
        k_edge<<<warp_blocks, 256>>>(l);
        k_mlp<0><<<mlp_blocks, 256>>>(p_aggr,
                                      uw1 + (size_t)l * HID * HID, ub1 + (size_t)l * HID,
                                      uw2 + (size_t)l * HID * HID, ub2 + (size_t)l * HID,
                                      p_h, NN);
    }
    // output block: e2 = ssp(ssp(h@ow1+b1)@ow2+b2) stored into g_aggr
    k_mlp<1><<<mlp_blocks, 256>>>(p_h, ow1, ob1, ow2, ob2, p_aggr, NN);
    k_zero_out<<<2, 256>>>(out);
    k_energy<<<warp_blocks, 256>>>(batch, ow3, ob3, out);
}